// round 13
// baseline (speedup 1.0000x reference)
#include <cuda_runtime.h>
#include <cuda_fp16.h>
#include <cstdint>

typedef __half h16;

// ---------------- problem constants ----------------
#define NB    8
#define SQ    1024
#define SKV   1024
#define EDIM  1024
#define VOC   32000
#define NL    6
#define MTOT  (NB * SQ)        // 8192
#define SCALE_Q 0.125f

// ---------------- device scratch ----------------
__device__ __align__(16) h16  g_x  [MTOT * EDIM];
__device__ __align__(16) h16  g_T  [MTOT * EDIM];
__device__ __align__(16) h16  g_q  [MTOT * EDIM];
__device__ __align__(16) h16  g_p  [NB * SQ * SKV];
__device__ __align__(16) h16  g_o  [MTOT * EDIM];
__device__ __align__(16) h16  g_k  [MTOT * EDIM];
__device__ __align__(16) h16  g_vT [MTOT * EDIM];
__device__ __align__(16) h16  g_lin[VOC * EDIM];
__device__ __align__(16) h16  g_w  [3 * EDIM * EDIM];
__device__ __align__(16) h16  g_wo [EDIM * EDIM];
__device__ float g_scores[NB * SQ * SKV];

// ---------------- helpers ----------------
__device__ __forceinline__ uint32_t pack2(h16 a, h16 b) {
    __half2 p = __halves2half2(a, b);
    return *reinterpret_cast<uint32_t*>(&p);
}

// fp32 -> fp16, vectorized (n4 = count of float4)
__global__ void conv_h(const float* __restrict__ src, h16* __restrict__ h, size_t n4) {
    size_t stride = (size_t)gridDim.x * blockDim.x;
    for (size_t i = (size_t)blockIdx.x * blockDim.x + threadIdx.x; i < n4; i += stride) {
        float4 v = reinterpret_cast<const float4*>(src)[i];
        reinterpret_cast<uint2*>(h)[i] =
            make_uint2(pack2(__float2half_rn(v.x), __float2half_rn(v.y)),
                       pack2(__float2half_rn(v.z), __float2half_rn(v.w)));
    }
}

// embedding gather -> fp16; one block (256 thr) per row, 4 cols/thread
__global__ void gather_h(const int* __restrict__ idx, const float* __restrict__ embed,
                         h16* __restrict__ x) {
    int row = blockIdx.x;
    int tok = idx[row];
    const float4* src = reinterpret_cast<const float4*>(embed + (size_t)tok * EDIM);
    float4 v = src[threadIdx.x];
    reinterpret_cast<uint2*>(x + (size_t)row * EDIM)[threadIdx.x] =
        make_uint2(pack2(__float2half_rn(v.x), __float2half_rn(v.y)),
                   pack2(__float2half_rn(v.z), __float2half_rn(v.w)));
}

// row softmax over 1024 cols -> fp16; 256 threads/row
__global__ void softmax_h(const float* __restrict__ S, h16* __restrict__ P) {
    int row = blockIdx.x;
    int t = threadIdx.x;
    int lane = t & 31, w = t >> 5;
    float4 v = reinterpret_cast<const float4*>(S + (size_t)row * SKV)[t];

    float m = fmaxf(fmaxf(v.x, v.y), fmaxf(v.z, v.w));
#pragma unroll
    for (int off = 16; off > 0; off >>= 1)
        m = fmaxf(m, __shfl_xor_sync(0xFFFFFFFFu, m, off));
    __shared__ float red[8];
    if (lane == 0) red[w] = m;
    __syncthreads();
    float mx = red[0];
#pragma unroll
    for (int i = 1; i < 8; i++) mx = fmaxf(mx, red[i]);

    v.x = __expf(v.x - mx); v.y = __expf(v.y - mx);
    v.z = __expf(v.z - mx); v.w = __expf(v.w - mx);
    float s = v.x + v.y + v.z + v.w;
#pragma unroll
    for (int off = 16; off > 0; off >>= 1)
        s += __shfl_xor_sync(0xFFFFFFFFu, s, off);
    __shared__ float red2[8];
    if (lane == 0) red2[w] = s;
    __syncthreads();
    float tot = red2[0];
#pragma unroll
    for (int i = 1; i < 8; i++) tot += red2[i];
    float inv = 1.f / tot;

    reinterpret_cast<uint2*>(P + (size_t)row * SKV)[t] =
        make_uint2(pack2(__float2half_rn(v.x * inv), __float2half_rn(v.y * inv)),
                   pack2(__float2half_rn(v.z * inv), __float2half_rn(v.w * inv)));
}

// ---------------- mma.sync fp16 GEMM, 128x128x32 tile, 256 threads, 2 CTAs/SM ----------------
// C[m,n] = alpha * sum_k A[m,k]*B[n,k] + bias[n]; single-term fp16, fp32 acc.
// 8 warps as 2(m) x 4(n); warp tile 64x32; 5-stage cp.async.
// Inner loop: ALL 12 ldmatrix for the BK=32 iter hoisted before the 32 HMMAs
// (frags 48 regs + acc 64 = 112 < 128) so ks=0 compute hides ks=1 load latency.

#define BK        32
#define BM        128
#define BN        128
#define NTHR      256
#define LDROW     80
#define A_BYTES   (BM * LDROW)                // 10240
#define B_BYTES   (BN * LDROW)                // 10240
#define NSTAGE    5
#define STAGE_B   (A_BYTES + B_BYTES)         // 20480
#define GSMEM     (NSTAGE * STAGE_B)          // 102400 (>= epilogue 128*132*4 = 67584)
#define GROUP_Y   8

__device__ __forceinline__ uint32_t smem_u32(const void* p) {
    uint32_t a;
    asm("{ .reg .u64 t; cvta.to.shared.u64 t, %1; cvt.u32.u64 %0, t; }" : "=r"(a) : "l"(p));
    return a;
}

__device__ __forceinline__ void ldm_x4(uint32_t& r0, uint32_t& r1, uint32_t& r2,
                                       uint32_t& r3, uint32_t addr) {
    asm volatile("ldmatrix.sync.aligned.m8n8.x4.shared.b16 {%0,%1,%2,%3}, [%4];"
                 : "=r"(r0), "=r"(r1), "=r"(r2), "=r"(r3) : "r"(addr));
}

__device__ __forceinline__ void mma16816(float* c, const uint32_t* a, const uint32_t* b) {
    asm volatile(
        "mma.sync.aligned.m16n8k16.row.col.f32.f16.f16.f32 "
        "{%0,%1,%2,%3}, {%4,%5,%6,%7}, {%8,%9}, {%0,%1,%2,%3};"
        : "+f"(c[0]), "+f"(c[1]), "+f"(c[2]), "+f"(c[3])
        : "r"(a[0]), "r"(a[1]), "r"(a[2]), "r"(a[3]), "r"(b[0]), "r"(b[1]));
}

__device__ __forceinline__ void fill_stage(uint32_t sbase,
    const h16* __restrict__ A0, const h16* __restrict__ B0,
    int K, int k0, int tid)
{
    // A: 128 rows x 4 chunks of 16B = 512 tasks, 256 threads -> 2 rounds
#pragma unroll
    for (int j = 0; j < 2; j++) {
        int e = tid + j * NTHR;
        int row = e >> 2, c = e & 3;
        uint32_t dst = sbase + row * LDROW + c * 16;
        uint64_t src = __cvta_generic_to_global((const void*)(A0 + (size_t)row * K + k0 + c * 8));
        asm volatile("cp.async.cg.shared.global [%0], [%1], 16;" :: "r"(dst), "l"(src));
    }
    // B: 128 rows x 4 chunks = 512 tasks -> 2 rounds
#pragma unroll
    for (int j = 0; j < 2; j++) {
        int e = tid + j * NTHR;
        int row = e >> 2, c = e & 3;
        uint32_t dst = sbase + A_BYTES + row * LDROW + c * 16;
        uint64_t src = __cvta_generic_to_global((const void*)(B0 + (size_t)row * K + k0 + c * 8));
        asm volatile("cp.async.cg.shared.global [%0], [%1], 16;" :: "r"(dst), "l"(src));
    }
    asm volatile("cp.async.commit_group;" ::: "memory");
}

template <bool TRANS>
__global__ void __launch_bounds__(NTHR, 2)
gemm_mma(const h16* __restrict__ A, size_t sA,
         const h16* __restrict__ Bh, size_t sB,
         float* __restrict__ Cf, h16* __restrict__ Ch, size_t sC,
         int M, int N, int K, int ldc, float alpha, const float* __restrict__ bias)
{
    extern __shared__ __align__(128) char smem[];
    const uint32_t sb = smem_u32(smem);
    const int tid  = threadIdx.x;
    const int wid  = tid >> 5;
    const int lane = tid & 31;
    const int wm = wid >> 2;                  // 0..1 : 64-row block
    const int wn = wid & 3;                   // 0..3 : 32-col block
    const int z  = blockIdx.z;

    // grouped rasterization
    int lin = blockIdx.y * gridDim.x + blockIdx.x;
    int gsz = GROUP_Y * gridDim.x;
    int grp = lin / gsz, rem = lin % gsz;
    int span = min(GROUP_Y, (int)gridDim.y - grp * GROUP_Y);
    int by = grp * GROUP_Y + rem % span;
    int bx = rem / span;
    const int m0 = by * BM;
    const int n0 = bx * BN;

    const h16* A0 = A  + (size_t)z * sA + (size_t)m0 * K;
    const h16* B0 = Bh + (size_t)z * sB + (size_t)n0 * K;

    const uint32_t a_base = (uint32_t)((wm * 64 + (lane & 15)) * LDROW + (lane >> 4) * 16);
    const uint32_t b_base = (uint32_t)((wn * 32 + (lane >> 4) * 8 + (lane & 7)) * LDROW
                                       + ((lane >> 3) & 1) * 16);

    float acc[4][4][4];
#pragma unroll
    for (int i = 0; i < 4; i++)
#pragma unroll
        for (int j = 0; j < 4; j++)
#pragma unroll
            for (int r = 0; r < 4; r++) acc[i][j][r] = 0.f;

    const int KT = K / BK;

#pragma unroll
    for (int s = 0; s < NSTAGE - 1; s++)
        fill_stage(sb + s * STAGE_B, A0, B0, K, s * BK, tid);

    int stage = 0;
    for (int kt = 0; kt < KT; kt++) {
        asm volatile("cp.async.wait_group %0;" :: "n"(NSTAGE - 2) : "memory");
        __syncthreads();

        int f = kt + NSTAGE - 1;
        if (f < KT)
            fill_stage(sb + (f % NSTAGE) * STAGE_B, A0, B0, K, f * BK, tid);
        else
            asm volatile("cp.async.commit_group;" ::: "memory");  // keep group-count semantics

        const uint32_t sA_ = sb + stage * STAGE_B;
        const uint32_t sB_ = sA_ + A_BYTES;

        // ---- hoisted loads: all 12 ldmatrix for both ks before any HMMA ----
        uint32_t ah[2][4][4], bh[2][4][2];
#pragma unroll
        for (int ks = 0; ks < 2; ks++) {
            const uint32_t ko = ks * 32;
#pragma unroll
            for (int mi = 0; mi < 4; mi++) {
                uint32_t off = a_base + mi * 16 * LDROW + ko;
                ldm_x4(ah[ks][mi][0], ah[ks][mi][1], ah[ks][mi][2], ah[ks][mi][3], sA_ + off);
            }
#pragma unroll
            for (int p = 0; p < 2; p++) {
                uint32_t off = b_base + p * 16 * LDROW + ko;
                ldm_x4(bh[ks][2 * p][0], bh[ks][2 * p][1],
                       bh[ks][2 * p + 1][0], bh[ks][2 * p + 1][1], sB_ + off);
            }
        }
        // ---- compute: 32 HMMAs; ks=0 stream covers ks=1 load latency ----
#pragma unroll
        for (int ks = 0; ks < 2; ks++)
#pragma unroll
            for (int mi = 0; mi < 4; mi++)
#pragma unroll
                for (int ni = 0; ni < 4; ni++)
                    mma16816(acc[mi][ni], ah[ks][mi], bh[ks][ni]);

        stage = (stage + 1 == NSTAGE) ? 0 : stage + 1;
    }

    asm volatile("cp.async.wait_group 0;" ::: "memory");
    __syncthreads();

    // ---------------- epilogue (128x128, LD=132 both orientations) ----------------
    const int LD = 132;
    float* SE = reinterpret_cast<float*>(smem);
    const int tr = lane >> 2;
    const int tc = (lane & 3) * 2;
#pragma unroll
    for (int mi = 0; mi < 4; mi++)
#pragma unroll
        for (int ni = 0; ni < 4; ni++) {
            int r0 = wm * 64 + mi * 16 + tr;
            int c0 = wn * 32 + ni * 8 + tc;
            if (!TRANS) {
                SE[r0 * LD + c0]           = acc[mi][ni][0];
                SE[r0 * LD + c0 + 1]       = acc[mi][ni][1];
                SE[(r0 + 8) * LD + c0]     = acc[mi][ni][2];
                SE[(r0 + 8) * LD + c0 + 1] = acc[mi][ni][3];
            } else {
                SE[c0 * LD + r0]           = acc[mi][ni][0];
                SE[(c0 + 1) * LD + r0]     = acc[mi][ni][1];
                SE[c0 * LD + r0 + 8]       = acc[mi][ni][2];
                SE[(c0 + 1) * LD + r0 + 8] = acc[mi][ni][3];
            }
        }
    __syncthreads();

    const int OB = TRANS ? n0 : m0;
    const int IB = TRANS ? m0 : n0;
#pragma unroll
    for (int i = 0; i < 16; i++) {
        int e = tid + i * NTHR;               // 0..4095 float4s
        int row = e >> 5;
        int c4 = (e & 31) * 4;
        float4 v = *reinterpret_cast<float4*>(&SE[row * LD + c4]);
        v.x *= alpha; v.y *= alpha; v.z *= alpha; v.w *= alpha;
        if (!TRANS && bias) {
            v.x += bias[n0 + c4];
            v.y += bias[n0 + c4 + 1];
            v.z += bias[n0 + c4 + 2];
            v.w += bias[n0 + c4 + 3];
        }
        size_t o = (size_t)z * sC + (size_t)(OB + row) * ldc + IB + c4;
        if (Cf) *reinterpret_cast<float4*>(Cf + o) = v;
        if (Ch) {
            *reinterpret_cast<uint2*>(Ch + o) =
                make_uint2(pack2(__float2half_rn(v.x), __float2half_rn(v.y)),
                           pack2(__float2half_rn(v.z), __float2half_rn(v.w)));
        }
    }
}

// ---------------- host-side launcher ----------------
static void launch_gemm(bool trans,
                        const h16* A, size_t sA,
                        const h16* B, size_t sB,
                        float* Cf, h16* Ch, size_t sC,
                        int M, int N, int K, int ldc, float alpha,
                        const float* bias, int batch) {
    dim3 grid(N / BN, M / BM, batch);
    if (trans)
        gemm_mma<true><<<grid, NTHR, GSMEM>>>(A, sA, B, sB, Cf, Ch, sC,
                                              M, N, K, ldc, alpha, bias);
    else
        gemm_mma<false><<<grid, NTHR, GSMEM>>>(A, sA, B, sB, Cf, Ch, sC,
                                               M, N, K, ldc, alpha, bias);
}

#define SYM(var, sym)                                   \
    do {                                                \
        void* _p = nullptr;                             \
        cudaGetSymbolAddress(&_p, sym);                 \
        var = (decltype(var))_p;                        \
    } while (0)

extern "C" void kernel_launch(void* const* d_in, const int* in_sizes, int n_in,
                              void* d_out, int out_size) {
    const int*   input_text = (const int*)d_in[0];
    const float* target     = (const float*)d_in[1];
    const float* embed      = (const float*)d_in[2];
    const float* in_proj_w  = (const float*)d_in[3];
    const float* out_w      = (const float*)d_in[4];
    const float* out_b      = (const float*)d_in[5];
    const float* lin_w      = (const float*)d_in[6];
    const float* lin_b      = (const float*)d_in[7];
    float*       logits     = (float*)d_out;

    cudaFuncSetAttribute(gemm_mma<false>,
                         cudaFuncAttributeMaxDynamicSharedMemorySize, GSMEM);
    cudaFuncSetAttribute(gemm_mma<true>,
                         cudaFuncAttributeMaxDynamicSharedMemorySize, GSMEM);

    h16 *x, *T, *q, *p, *o, *k, *vT, *lin, *w, *wo;
    float* sc;
    SYM(x, g_x);   SYM(T, g_T);   SYM(q, g_q);   SYM(p, g_p);   SYM(o, g_o);
    SYM(k, g_k);   SYM(vT, g_vT); SYM(lin, g_lin);
    SYM(w, g_w);   SYM(wo, g_wo);
    SYM(sc, g_scores);

    gather_h<<<MTOT, 256>>>(input_text, embed, x);              // launch 1
    conv_h<<<4096, 256>>>(target, T, (size_t)MTOT * EDIM / 4);  // launch 2

    const size_t EE = (size_t)EDIM * EDIM;

    for (int l = 0; l < NL; l++) {
        conv_h<<<3072, 256>>>(in_proj_w + (size_t)l * 3 * EE, w, 3 * EE / 4);  // 3

        // q = (x @ Wq^T) * SCALE      <- 4th launch: profiled GEMM
        launch_gemm(false, x, 0, w, 0,
                    nullptr, q, 0,
                    MTOT, EDIM, EDIM, EDIM, SCALE_Q, nullptr, 1);

        conv_h<<<1024, 256>>>(out_w + (size_t)l * EE, wo, EE / 4);

        // k = target @ Wk^T
        launch_gemm(false, T, 0, w + EE, 0,
                    nullptr, k, 0,
                    MTOT, EDIM, EDIM, EDIM, 1.f, nullptr, 1);
        // vT[b] = (target_b @ Wv^T)^T  (transposed store)
        launch_gemm(true, T, (size_t)SKV * EDIM, w + 2 * EE, 0,
                    nullptr, vT, (size_t)EDIM * SKV,
                    SKV, EDIM, EDIM, SKV, 1.f, nullptr, NB);
        // scores[b] = q_b @ k_b^T      (fp32 out)
        launch_gemm(false, q, (size_t)SQ * EDIM, k, (size_t)SKV * EDIM,
                    sc, nullptr, (size_t)SQ * SKV,
                    SQ, SKV, EDIM, SKV, 1.f, nullptr, NB);
        softmax_h<<<NB * SQ, 256>>>(sc, p);
        // o[b] = attn_b @ vT_b^T
        launch_gemm(false, p, (size_t)SQ * SKV, vT, (size_t)EDIM * SKV,
                    nullptr, o, (size_t)SQ * EDIM,
                    SQ, EDIM, SKV, EDIM, 1.f, nullptr, NB);
        // x = o @ out_w^T + out_b
        launch_gemm(false, o, 0, wo, 0,
                    nullptr, x, 0,
                    MTOT, EDIM, EDIM, EDIM, 1.f, out_b + (size_t)l * EDIM, 1);
    }

    // logits = x @ lin_w^T + lin_b     (fp32 out)
    conv_h<<<8192, 256>>>(lin_w, lin, (size_t)VOC * EDIM / 4);
    launch_gemm(false, x, 0, lin, 0,
                logits, nullptr, 0,
                MTOT, VOC, EDIM, VOC, 1.f, lin_b, 1);
}

// round 14
// speedup vs baseline: 1.1442x; 1.1442x over previous
#include <cuda_runtime.h>
#include <cuda_fp16.h>
#include <cstdint>

typedef __half h16;

// ---------------- problem constants ----------------
#define NB    8
#define SQ    1024
#define SKV   1024
#define EDIM  1024
#define VOC   32000
#define NL    6
#define MTOT  (NB * SQ)        // 8192
#define SCALE_Q 0.125f

// ---------------- device scratch ----------------
__device__ __align__(16) h16  g_x  [MTOT * EDIM];
__device__ __align__(16) h16  g_T  [MTOT * EDIM];
__device__ __align__(16) h16  g_q  [MTOT * EDIM];
__device__ __align__(16) h16  g_p  [NB * SQ * SKV];
__device__ __align__(16) h16  g_o  [MTOT * EDIM];
__device__ __align__(16) h16  g_k  [MTOT * EDIM];
__device__ __align__(16) h16  g_vT [MTOT * EDIM];
__device__ __align__(16) h16  g_lin[VOC * EDIM];
__device__ __align__(16) h16  g_w  [3 * EDIM * EDIM];
__device__ __align__(16) h16  g_wo [EDIM * EDIM];
__device__ float g_scores[NB * SQ * SKV];

// ---------------- helpers ----------------
__device__ __forceinline__ uint32_t pack2(h16 a, h16 b) {
    __half2 p = __halves2half2(a, b);
    return *reinterpret_cast<uint32_t*>(&p);
}

// fp32 -> fp16, vectorized (n4 = count of float4)
__global__ void conv_h(const float* __restrict__ src, h16* __restrict__ h, size_t n4) {
    size_t stride = (size_t)gridDim.x * blockDim.x;
    for (size_t i = (size_t)blockIdx.x * blockDim.x + threadIdx.x; i < n4; i += stride) {
        float4 v = reinterpret_cast<const float4*>(src)[i];
        reinterpret_cast<uint2*>(h)[i] =
            make_uint2(pack2(__float2half_rn(v.x), __float2half_rn(v.y)),
                       pack2(__float2half_rn(v.z), __float2half_rn(v.w)));
    }
}

// embedding gather -> fp16; one block (256 thr) per row, 4 cols/thread
__global__ void gather_h(const int* __restrict__ idx, const float* __restrict__ embed,
                         h16* __restrict__ x) {
    int row = blockIdx.x;
    int tok = idx[row];
    const float4* src = reinterpret_cast<const float4*>(embed + (size_t)tok * EDIM);
    float4 v = src[threadIdx.x];
    reinterpret_cast<uint2*>(x + (size_t)row * EDIM)[threadIdx.x] =
        make_uint2(pack2(__float2half_rn(v.x), __float2half_rn(v.y)),
                   pack2(__float2half_rn(v.z), __float2half_rn(v.w)));
}

// row softmax over 1024 cols -> fp16; 256 threads/row
__global__ void softmax_h(const float* __restrict__ S, h16* __restrict__ P) {
    int row = blockIdx.x;
    int t = threadIdx.x;
    int lane = t & 31, w = t >> 5;
    float4 v = reinterpret_cast<const float4*>(S + (size_t)row * SKV)[t];

    float m = fmaxf(fmaxf(v.x, v.y), fmaxf(v.z, v.w));
#pragma unroll
    for (int off = 16; off > 0; off >>= 1)
        m = fmaxf(m, __shfl_xor_sync(0xFFFFFFFFu, m, off));
    __shared__ float red[8];
    if (lane == 0) red[w] = m;
    __syncthreads();
    float mx = red[0];
#pragma unroll
    for (int i = 1; i < 8; i++) mx = fmaxf(mx, red[i]);

    v.x = __expf(v.x - mx); v.y = __expf(v.y - mx);
    v.z = __expf(v.z - mx); v.w = __expf(v.w - mx);
    float s = v.x + v.y + v.z + v.w;
#pragma unroll
    for (int off = 16; off > 0; off >>= 1)
        s += __shfl_xor_sync(0xFFFFFFFFu, s, off);
    __shared__ float red2[8];
    if (lane == 0) red2[w] = s;
    __syncthreads();
    float tot = red2[0];
#pragma unroll
    for (int i = 1; i < 8; i++) tot += red2[i];
    float inv = 1.f / tot;

    reinterpret_cast<uint2*>(P + (size_t)row * SKV)[t] =
        make_uint2(pack2(__float2half_rn(v.x * inv), __float2half_rn(v.y * inv)),
                   pack2(__float2half_rn(v.z * inv), __float2half_rn(v.w * inv)));
}

// ---------------- mma.sync fp16 GEMM, 128x128x64 tile, 256 threads, 2 CTAs/SM ----------------
// C[m,n] = alpha * sum_k A[m,k]*B[n,k] + bias[n]; single-term fp16, fp32 acc.
// 8 warps as 2(m) x 4(n); warp tile 64x32; BK=64, 2-stage cp.async.
// Halves per-tile barrier/wait counts vs BK=32 (16 iters instead of 32).

#define BK        64
#define BM        128
#define BN        128
#define NTHR      256
#define LDROW     144                        // 128B data + 16B pad (4-bank row shift)
#define A_BYTES   (BM * LDROW)               // 18432
#define B_BYTES   (BN * LDROW)               // 18432
#define NSTAGE    2
#define STAGE_B   (A_BYTES + B_BYTES)        // 36864
#define GSMEM     (NSTAGE * STAGE_B)         // 73728 (>= epilogue 128*132*4 = 67584)
#define GROUP_Y   8

__device__ __forceinline__ uint32_t smem_u32(const void* p) {
    uint32_t a;
    asm("{ .reg .u64 t; cvta.to.shared.u64 t, %1; cvt.u32.u64 %0, t; }" : "=r"(a) : "l"(p));
    return a;
}

__device__ __forceinline__ void ldm_x4(uint32_t& r0, uint32_t& r1, uint32_t& r2,
                                       uint32_t& r3, uint32_t addr) {
    asm volatile("ldmatrix.sync.aligned.m8n8.x4.shared.b16 {%0,%1,%2,%3}, [%4];"
                 : "=r"(r0), "=r"(r1), "=r"(r2), "=r"(r3) : "r"(addr));
}

__device__ __forceinline__ void mma16816(float* c, const uint32_t* a, const uint32_t* b) {
    asm volatile(
        "mma.sync.aligned.m16n8k16.row.col.f32.f16.f16.f32 "
        "{%0,%1,%2,%3}, {%4,%5,%6,%7}, {%8,%9}, {%0,%1,%2,%3};"
        : "+f"(c[0]), "+f"(c[1]), "+f"(c[2]), "+f"(c[3])
        : "r"(a[0]), "r"(a[1]), "r"(a[2]), "r"(a[3]), "r"(b[0]), "r"(b[1]));
}

__device__ __forceinline__ void fill_stage(uint32_t sbase,
    const h16* __restrict__ A0, const h16* __restrict__ B0,
    int K, int k0, int tid)
{
    // A: 128 rows x 8 chunks of 16B = 1024 tasks, 256 threads -> 4 rounds
#pragma unroll
    for (int j = 0; j < 4; j++) {
        int e = tid + j * NTHR;
        int row = e >> 3, c = e & 7;
        uint32_t dst = sbase + row * LDROW + c * 16;
        uint64_t src = __cvta_generic_to_global((const void*)(A0 + (size_t)row * K + k0 + c * 8));
        asm volatile("cp.async.cg.shared.global [%0], [%1], 16;" :: "r"(dst), "l"(src));
    }
    // B: 128 rows x 8 chunks = 1024 tasks -> 4 rounds
#pragma unroll
    for (int j = 0; j < 4; j++) {
        int e = tid + j * NTHR;
        int row = e >> 3, c = e & 7;
        uint32_t dst = sbase + A_BYTES + row * LDROW + c * 16;
        uint64_t src = __cvta_generic_to_global((const void*)(B0 + (size_t)row * K + k0 + c * 8));
        asm volatile("cp.async.cg.shared.global [%0], [%1], 16;" :: "r"(dst), "l"(src));
    }
    asm volatile("cp.async.commit_group;" ::: "memory");
}

template <bool TRANS>
__global__ void __launch_bounds__(NTHR, 2)
gemm_mma(const h16* __restrict__ A, size_t sA,
         const h16* __restrict__ Bh, size_t sB,
         float* __restrict__ Cf, h16* __restrict__ Ch, size_t sC,
         int M, int N, int K, int ldc, float alpha, const float* __restrict__ bias)
{
    extern __shared__ __align__(128) char smem[];
    const uint32_t sb = smem_u32(smem);
    const int tid  = threadIdx.x;
    const int wid  = tid >> 5;
    const int lane = tid & 31;
    const int wm = wid >> 2;                  // 0..1 : 64-row block
    const int wn = wid & 3;                   // 0..3 : 32-col block
    const int z  = blockIdx.z;

    // grouped rasterization
    int lin = blockIdx.y * gridDim.x + blockIdx.x;
    int gsz = GROUP_Y * gridDim.x;
    int grp = lin / gsz, rem = lin % gsz;
    int span = min(GROUP_Y, (int)gridDim.y - grp * GROUP_Y);
    int by = grp * GROUP_Y + rem % span;
    int bx = rem / span;
    const int m0 = by * BM;
    const int n0 = bx * BN;

    const h16* A0 = A  + (size_t)z * sA + (size_t)m0 * K;
    const h16* B0 = Bh + (size_t)z * sB + (size_t)n0 * K;

    const uint32_t a_base = (uint32_t)((wm * 64 + (lane & 15)) * LDROW + (lane >> 4) * 16);
    const uint32_t b_base = (uint32_t)((wn * 32 + (lane >> 4) * 8 + (lane & 7)) * LDROW
                                       + ((lane >> 3) & 1) * 16);

    float acc[4][4][4];
#pragma unroll
    for (int i = 0; i < 4; i++)
#pragma unroll
        for (int j = 0; j < 4; j++)
#pragma unroll
            for (int r = 0; r < 4; r++) acc[i][j][r] = 0.f;

    const int KT = K / BK;                    // 16 iters for K=1024

    fill_stage(sb, A0, B0, K, 0, tid);        // prefill stage 0

    int stage = 0;
    for (int kt = 0; kt < KT; kt++) {
        asm volatile("cp.async.wait_group 0;" ::: "memory");
        __syncthreads();

        int f = kt + 1;
        if (f < KT)
            fill_stage(sb + (f & 1) * STAGE_B, A0, B0, K, f * BK, tid);

        const uint32_t sA_ = sb + stage * STAGE_B;
        const uint32_t sB_ = sA_ + A_BYTES;

#pragma unroll
        for (int ks = 0; ks < 4; ks++) {      // 4 k-steps of 16
            const uint32_t ko = ks * 32;      // 16 fp16 = 32 bytes
            uint32_t ah[4][4], bh[4][2];
#pragma unroll
            for (int mi = 0; mi < 4; mi++) {
                uint32_t off = a_base + mi * 16 * LDROW + ko;
                ldm_x4(ah[mi][0], ah[mi][1], ah[mi][2], ah[mi][3], sA_ + off);
            }
#pragma unroll
            for (int p = 0; p < 2; p++) {
                uint32_t off = b_base + p * 16 * LDROW + ko;
                ldm_x4(bh[2 * p][0], bh[2 * p][1], bh[2 * p + 1][0], bh[2 * p + 1][1], sB_ + off);
            }
#pragma unroll
            for (int mi = 0; mi < 4; mi++)
#pragma unroll
                for (int ni = 0; ni < 4; ni++)
                    mma16816(acc[mi][ni], ah[mi], bh[ni]);
        }
        stage ^= 1;
    }

    __syncthreads();

    // ---------------- epilogue (128x128, LD=132 both orientations) ----------------
    const int LD = 132;
    float* SE = reinterpret_cast<float*>(smem);
    const int tr = lane >> 2;
    const int tc = (lane & 3) * 2;
#pragma unroll
    for (int mi = 0; mi < 4; mi++)
#pragma unroll
        for (int ni = 0; ni < 4; ni++) {
            int r0 = wm * 64 + mi * 16 + tr;
            int c0 = wn * 32 + ni * 8 + tc;
            if (!TRANS) {
                SE[r0 * LD + c0]           = acc[mi][ni][0];
                SE[r0 * LD + c0 + 1]       = acc[mi][ni][1];
                SE[(r0 + 8) * LD + c0]     = acc[mi][ni][2];
                SE[(r0 + 8) * LD + c0 + 1] = acc[mi][ni][3];
            } else {
                SE[c0 * LD + r0]           = acc[mi][ni][0];
                SE[(c0 + 1) * LD + r0]     = acc[mi][ni][1];
                SE[c0 * LD + r0 + 8]       = acc[mi][ni][2];
                SE[(c0 + 1) * LD + r0 + 8] = acc[mi][ni][3];
            }
        }
    __syncthreads();

    const int OB = TRANS ? n0 : m0;
    const int IB = TRANS ? m0 : n0;
#pragma unroll
    for (int i = 0; i < 16; i++) {
        int e = tid + i * NTHR;               // 0..4095 float4s
        int row = e >> 5;
        int c4 = (e & 31) * 4;
        float4 v = *reinterpret_cast<float4*>(&SE[row * LD + c4]);
        v.x *= alpha; v.y *= alpha; v.z *= alpha; v.w *= alpha;
        if (!TRANS && bias) {
            v.x += bias[n0 + c4];
            v.y += bias[n0 + c4 + 1];
            v.z += bias[n0 + c4 + 2];
            v.w += bias[n0 + c4 + 3];
        }
        size_t o = (size_t)z * sC + (size_t)(OB + row) * ldc + IB + c4;
        if (Cf) *reinterpret_cast<float4*>(Cf + o) = v;
        if (Ch) {
            *reinterpret_cast<uint2*>(Ch + o) =
                make_uint2(pack2(__float2half_rn(v.x), __float2half_rn(v.y)),
                           pack2(__float2half_rn(v.z), __float2half_rn(v.w)));
        }
    }
}

// ---------------- host-side launcher ----------------
static void launch_gemm(bool trans,
                        const h16* A, size_t sA,
                        const h16* B, size_t sB,
                        float* Cf, h16* Ch, size_t sC,
                        int M, int N, int K, int ldc, float alpha,
                        const float* bias, int batch) {
    dim3 grid(N / BN, M / BM, batch);
    if (trans)
        gemm_mma<true><<<grid, NTHR, GSMEM>>>(A, sA, B, sB, Cf, Ch, sC,
                                              M, N, K, ldc, alpha, bias);
    else
        gemm_mma<false><<<grid, NTHR, GSMEM>>>(A, sA, B, sB, Cf, Ch, sC,
                                               M, N, K, ldc, alpha, bias);
}

#define SYM(var, sym)                                   \
    do {                                                \
        void* _p = nullptr;                             \
        cudaGetSymbolAddress(&_p, sym);                 \
        var = (decltype(var))_p;                        \
    } while (0)

extern "C" void kernel_launch(void* const* d_in, const int* in_sizes, int n_in,
                              void* d_out, int out_size) {
    const int*   input_text = (const int*)d_in[0];
    const float* target     = (const float*)d_in[1];
    const float* embed      = (const float*)d_in[2];
    const float* in_proj_w  = (const float*)d_in[3];
    const float* out_w      = (const float*)d_in[4];
    const float* out_b      = (const float*)d_in[5];
    const float* lin_w      = (const float*)d_in[6];
    const float* lin_b      = (const float*)d_in[7];
    float*       logits     = (float*)d_out;

    cudaFuncSetAttribute(gemm_mma<false>,
                         cudaFuncAttributeMaxDynamicSharedMemorySize, GSMEM);
    cudaFuncSetAttribute(gemm_mma<true>,
                         cudaFuncAttributeMaxDynamicSharedMemorySize, GSMEM);

    h16 *x, *T, *q, *p, *o, *k, *vT, *lin, *w, *wo;
    float* sc;
    SYM(x, g_x);   SYM(T, g_T);   SYM(q, g_q);   SYM(p, g_p);   SYM(o, g_o);
    SYM(k, g_k);   SYM(vT, g_vT); SYM(lin, g_lin);
    SYM(w, g_w);   SYM(wo, g_wo);
    SYM(sc, g_scores);

    gather_h<<<MTOT, 256>>>(input_text, embed, x);              // launch 1
    conv_h<<<4096, 256>>>(target, T, (size_t)MTOT * EDIM / 4);  // launch 2

    const size_t EE = (size_t)EDIM * EDIM;

    for (int l = 0; l < NL; l++) {
        conv_h<<<3072, 256>>>(in_proj_w + (size_t)l * 3 * EE, w, 3 * EE / 4);  // 3

        // q = (x @ Wq^T) * SCALE      <- 4th launch: profiled GEMM
        launch_gemm(false, x, 0, w, 0,
                    nullptr, q, 0,
                    MTOT, EDIM, EDIM, EDIM, SCALE_Q, nullptr, 1);

        conv_h<<<1024, 256>>>(out_w + (size_t)l * EE, wo, EE / 4);

        // k = target @ Wk^T
        launch_gemm(false, T, 0, w + EE, 0,
                    nullptr, k, 0,
                    MTOT, EDIM, EDIM, EDIM, 1.f, nullptr, 1);
        // vT[b] = (target_b @ Wv^T)^T  (transposed store)
        launch_gemm(true, T, (size_t)SKV * EDIM, w + 2 * EE, 0,
                    nullptr, vT, (size_t)EDIM * SKV,
                    SKV, EDIM, EDIM, SKV, 1.f, nullptr, NB);
        // scores[b] = q_b @ k_b^T      (fp32 out)
        launch_gemm(false, q, (size_t)SQ * EDIM, k, (size_t)SKV * EDIM,
                    sc, nullptr, (size_t)SQ * SKV,
                    SQ, SKV, EDIM, SKV, 1.f, nullptr, NB);
        softmax_h<<<NB * SQ, 256>>>(sc, p);
        // o[b] = attn_b @ vT_b^T
        launch_gemm(false, p, (size_t)SQ * SKV, vT, (size_t)EDIM * SKV,
                    nullptr, o, (size_t)SQ * EDIM,
                    SQ, EDIM, SKV, EDIM, 1.f, nullptr, NB);
        // x = o @ out_w^T + out_b
        launch_gemm(false, o, 0, wo, 0,
                    nullptr, x, 0,
                    MTOT, EDIM, EDIM, EDIM, 1.f, out_b + (size_t)l * EDIM, 1);
    }

    // logits = x @ lin_w^T + lin_b     (fp32 out)
    conv_h<<<8192, 256>>>(lin_w, lin, (size_t)VOC * EDIM / 4);
    launch_gemm(false, x, 0, lin, 0,
                logits, nullptr, 0,
                MTOT, VOC, EDIM, VOC, 1.f, lin_b, 1);
}

// round 15
// speedup vs baseline: 1.1457x; 1.0013x over previous
#include <cuda_runtime.h>
#include <cuda_fp16.h>
#include <cstdint>

typedef __half h16;

// ---------------- problem constants ----------------
#define NB    8
#define SQ    1024
#define SKV   1024
#define EDIM  1024
#define VOC   32000
#define NL    6
#define MTOT  (NB * SQ)        // 8192
#define SCALE_Q 0.125f

// ---------------- device scratch ----------------
__device__ __align__(16) h16  g_x  [MTOT * EDIM];
__device__ __align__(16) h16  g_T  [MTOT * EDIM];
__device__ __align__(16) h16  g_q  [MTOT * EDIM];
__device__ __align__(16) h16  g_p  [NB * SQ * SKV];
__device__ __align__(16) h16  g_o  [MTOT * EDIM];
__device__ __align__(16) h16  g_k  [MTOT * EDIM];
__device__ __align__(16) h16  g_vT [MTOT * EDIM];
__device__ __align__(16) h16  g_lin[VOC * EDIM];
__device__ __align__(16) h16  g_w  [3 * EDIM * EDIM];
__device__ __align__(16) h16  g_wo [EDIM * EDIM];
__device__ float g_scores[NB * SQ * SKV];

// ---------------- helpers ----------------
__device__ __forceinline__ uint32_t pack2(h16 a, h16 b) {
    __half2 p = __halves2half2(a, b);
    return *reinterpret_cast<uint32_t*>(&p);
}

// fp32 -> fp16, vectorized (n4 = count of float4)
__global__ void conv_h(const float* __restrict__ src, h16* __restrict__ h, size_t n4) {
    size_t stride = (size_t)gridDim.x * blockDim.x;
    for (size_t i = (size_t)blockIdx.x * blockDim.x + threadIdx.x; i < n4; i += stride) {
        float4 v = reinterpret_cast<const float4*>(src)[i];
        reinterpret_cast<uint2*>(h)[i] =
            make_uint2(pack2(__float2half_rn(v.x), __float2half_rn(v.y)),
                       pack2(__float2half_rn(v.z), __float2half_rn(v.w)));
    }
}

// embedding gather -> fp16; one block (256 thr) per row, 4 cols/thread
__global__ void gather_h(const int* __restrict__ idx, const float* __restrict__ embed,
                         h16* __restrict__ x) {
    int row = blockIdx.x;
    int tok = idx[row];
    const float4* src = reinterpret_cast<const float4*>(embed + (size_t)tok * EDIM);
    float4 v = src[threadIdx.x];
    reinterpret_cast<uint2*>(x + (size_t)row * EDIM)[threadIdx.x] =
        make_uint2(pack2(__float2half_rn(v.x), __float2half_rn(v.y)),
                   pack2(__float2half_rn(v.z), __float2half_rn(v.w)));
}

// row softmax over 1024 cols -> fp16; 256 threads/row
__global__ void softmax_h(const float* __restrict__ S, h16* __restrict__ P) {
    int row = blockIdx.x;
    int t = threadIdx.x;
    int lane = t & 31, w = t >> 5;
    float4 v = reinterpret_cast<const float4*>(S + (size_t)row * SKV)[t];

    float m = fmaxf(fmaxf(v.x, v.y), fmaxf(v.z, v.w));
#pragma unroll
    for (int off = 16; off > 0; off >>= 1)
        m = fmaxf(m, __shfl_xor_sync(0xFFFFFFFFu, m, off));
    __shared__ float red[8];
    if (lane == 0) red[w] = m;
    __syncthreads();
    float mx = red[0];
#pragma unroll
    for (int i = 1; i < 8; i++) mx = fmaxf(mx, red[i]);

    v.x = __expf(v.x - mx); v.y = __expf(v.y - mx);
    v.z = __expf(v.z - mx); v.w = __expf(v.w - mx);
    float s = v.x + v.y + v.z + v.w;
#pragma unroll
    for (int off = 16; off > 0; off >>= 1)
        s += __shfl_xor_sync(0xFFFFFFFFu, s, off);
    __shared__ float red2[8];
    if (lane == 0) red2[w] = s;
    __syncthreads();
    float tot = red2[0];
#pragma unroll
    for (int i = 1; i < 8; i++) tot += red2[i];
    float inv = 1.f / tot;

    reinterpret_cast<uint2*>(P + (size_t)row * SKV)[t] =
        make_uint2(pack2(__float2half_rn(v.x * inv), __float2half_rn(v.y * inv)),
                   pack2(__float2half_rn(v.z * inv), __float2half_rn(v.w * inv)));
}

// ---------------- mma.sync fp16 GEMM, 128x128x64 tile, 256 threads, 2 CTAs/SM ----------------
// C[m,n] = alpha * sum_k A[m,k]*B[n,k] + bias[n]; single-term fp16, fp32 acc.
// 8 warps as 2(m) x 4(n); warp tile 64x32; BK=64.
// non-TRANS: 3-stage cp.async + DIRECT global epilogue (no SMEM staging).
// TRANS:     2-stage cp.async + SMEM-staged transposed epilogue.

#define BK        64
#define BM        128
#define BN        128
#define NTHR      256
#define LDROW     144                        // 128B data + 16B pad
#define A_BYTES   (BM * LDROW)               // 18432
#define B_BYTES   (BN * LDROW)               // 18432
#define STAGE_B   (A_BYTES + B_BYTES)        // 36864
#define GSMEM_NT  (3 * STAGE_B)              // 110592 (3-stage, direct epilogue)
#define GSMEM_TR  (2 * STAGE_B)              // 73728  (2-stage; >= epilogue 67584)
#define GROUP_Y   8

__device__ __forceinline__ uint32_t smem_u32(const void* p) {
    uint32_t a;
    asm("{ .reg .u64 t; cvta.to.shared.u64 t, %1; cvt.u32.u64 %0, t; }" : "=r"(a) : "l"(p));
    return a;
}

__device__ __forceinline__ void ldm_x4(uint32_t& r0, uint32_t& r1, uint32_t& r2,
                                       uint32_t& r3, uint32_t addr) {
    asm volatile("ldmatrix.sync.aligned.m8n8.x4.shared.b16 {%0,%1,%2,%3}, [%4];"
                 : "=r"(r0), "=r"(r1), "=r"(r2), "=r"(r3) : "r"(addr));
}

__device__ __forceinline__ void mma16816(float* c, const uint32_t* a, const uint32_t* b) {
    asm volatile(
        "mma.sync.aligned.m16n8k16.row.col.f32.f16.f16.f32 "
        "{%0,%1,%2,%3}, {%4,%5,%6,%7}, {%8,%9}, {%0,%1,%2,%3};"
        : "+f"(c[0]), "+f"(c[1]), "+f"(c[2]), "+f"(c[3])
        : "r"(a[0]), "r"(a[1]), "r"(a[2]), "r"(a[3]), "r"(b[0]), "r"(b[1]));
}

__device__ __forceinline__ void fill_stage(uint32_t sbase,
    const h16* __restrict__ A0, const h16* __restrict__ B0,
    int K, int k0, int tid)
{
#pragma unroll
    for (int j = 0; j < 4; j++) {
        int e = tid + j * NTHR;
        int row = e >> 3, c = e & 7;
        uint32_t dst = sbase + row * LDROW + c * 16;
        uint64_t src = __cvta_generic_to_global((const void*)(A0 + (size_t)row * K + k0 + c * 8));
        asm volatile("cp.async.cg.shared.global [%0], [%1], 16;" :: "r"(dst), "l"(src));
    }
#pragma unroll
    for (int j = 0; j < 4; j++) {
        int e = tid + j * NTHR;
        int row = e >> 3, c = e & 7;
        uint32_t dst = sbase + A_BYTES + row * LDROW + c * 16;
        uint64_t src = __cvta_generic_to_global((const void*)(B0 + (size_t)row * K + k0 + c * 8));
        asm volatile("cp.async.cg.shared.global [%0], [%1], 16;" :: "r"(dst), "l"(src));
    }
    asm volatile("cp.async.commit_group;" ::: "memory");
}

template <bool TRANS>
__global__ void __launch_bounds__(NTHR, 2)
gemm_mma(const h16* __restrict__ A, size_t sA,
         const h16* __restrict__ Bh, size_t sB,
         float* __restrict__ Cf, h16* __restrict__ Ch, size_t sC,
         int M, int N, int K, int ldc, float alpha, const float* __restrict__ bias)
{
    extern __shared__ __align__(128) char smem[];
    const uint32_t sb = smem_u32(smem);
    const int tid  = threadIdx.x;
    const int wid  = tid >> 5;
    const int lane = tid & 31;
    const int wm = wid >> 2;                  // 0..1 : 64-row block
    const int wn = wid & 3;                   // 0..3 : 32-col block
    const int z  = blockIdx.z;
    constexpr int NSTAGE = TRANS ? 2 : 3;

    // grouped rasterization
    int lin = blockIdx.y * gridDim.x + blockIdx.x;
    int gsz = GROUP_Y * gridDim.x;
    int grp = lin / gsz, rem = lin % gsz;
    int span = min(GROUP_Y, (int)gridDim.y - grp * GROUP_Y);
    int by = grp * GROUP_Y + rem % span;
    int bx = rem / span;
    const int m0 = by * BM;
    const int n0 = bx * BN;

    const h16* A0 = A  + (size_t)z * sA + (size_t)m0 * K;
    const h16* B0 = Bh + (size_t)z * sB + (size_t)n0 * K;

    const uint32_t a_base = (uint32_t)((wm * 64 + (lane & 15)) * LDROW + (lane >> 4) * 16);
    const uint32_t b_base = (uint32_t)((wn * 32 + (lane >> 4) * 8 + (lane & 7)) * LDROW
                                       + ((lane >> 3) & 1) * 16);

    float acc[4][4][4];
#pragma unroll
    for (int i = 0; i < 4; i++)
#pragma unroll
        for (int j = 0; j < 4; j++)
#pragma unroll
            for (int r = 0; r < 4; r++) acc[i][j][r] = 0.f;

    const int KT = K / BK;                    // 16 iters for K=1024

#pragma unroll
    for (int s = 0; s < NSTAGE - 1; s++)
        fill_stage(sb + s * STAGE_B, A0, B0, K, s * BK, tid);

    int stage = 0;
    for (int kt = 0; kt < KT; kt++) {
        asm volatile("cp.async.wait_group %0;" :: "n"(NSTAGE - 2) : "memory");
        __syncthreads();

        int f = kt + NSTAGE - 1;
        if (f < KT)
            fill_stage(sb + (f % NSTAGE) * STAGE_B, A0, B0, K, f * BK, tid);
        else
            asm volatile("cp.async.commit_group;" ::: "memory");  // keep group-count semantics

        const uint32_t sA_ = sb + stage * STAGE_B;
        const uint32_t sB_ = sA_ + A_BYTES;

#pragma unroll
        for (int ks = 0; ks < 4; ks++) {      // 4 k-steps of 16
            const uint32_t ko = ks * 32;      // 16 fp16 = 32 bytes
            uint32_t ah[4][4], bh[4][2];
#pragma unroll
            for (int mi = 0; mi < 4; mi++) {
                uint32_t off = a_base + mi * 16 * LDROW + ko;
                ldm_x4(ah[mi][0], ah[mi][1], ah[mi][2], ah[mi][3], sA_ + off);
            }
#pragma unroll
            for (int p = 0; p < 2; p++) {
                uint32_t off = b_base + p * 16 * LDROW + ko;
                ldm_x4(bh[2 * p][0], bh[2 * p][1], bh[2 * p + 1][0], bh[2 * p + 1][1], sB_ + off);
            }
#pragma unroll
            for (int mi = 0; mi < 4; mi++)
#pragma unroll
                for (int ni = 0; ni < 4; ni++)
                    mma16816(acc[mi][ni], ah[mi], bh[ni]);
        }
        stage = (stage + 1 == NSTAGE) ? 0 : stage + 1;
    }

    // ---------------- epilogue ----------------
    const int tr = lane >> 2;                 // 0..7
    const int tc = (lane & 3) * 2;            // 0,2,4,6

    if (!TRANS) {
        // DIRECT global stores: fragment (c, c+1) pairs are contiguous.
#pragma unroll
        for (int mi = 0; mi < 4; mi++)
#pragma unroll
            for (int ni = 0; ni < 4; ni++) {
                int gr = m0 + wm * 64 + mi * 16 + tr;
                int gc = n0 + wn * 32 + ni * 8 + tc;
                float v0 = acc[mi][ni][0] * alpha;
                float v1 = acc[mi][ni][1] * alpha;
                float v2 = acc[mi][ni][2] * alpha;
                float v3 = acc[mi][ni][3] * alpha;
                if (bias) {
                    float b0 = bias[gc], b1 = bias[gc + 1];
                    v0 += b0; v1 += b1; v2 += b0; v3 += b1;
                }
                size_t o0 = (size_t)z * sC + (size_t)gr * ldc + gc;
                size_t o1 = o0 + (size_t)8 * ldc;
                if (Cf) {
                    *reinterpret_cast<float2*>(Cf + o0) = make_float2(v0, v1);
                    *reinterpret_cast<float2*>(Cf + o1) = make_float2(v2, v3);
                }
                if (Ch) {
                    *reinterpret_cast<uint32_t*>(Ch + o0) =
                        pack2(__float2half_rn(v0), __float2half_rn(v1));
                    *reinterpret_cast<uint32_t*>(Ch + o1) =
                        pack2(__float2half_rn(v2), __float2half_rn(v3));
                }
            }
    } else {
        // staged transposed epilogue (vT path only)
        asm volatile("cp.async.wait_group 0;" ::: "memory");
        __syncthreads();
        const int LD = 132;
        float* SE = reinterpret_cast<float*>(smem);
#pragma unroll
        for (int mi = 0; mi < 4; mi++)
#pragma unroll
            for (int ni = 0; ni < 4; ni++) {
                int r0 = wm * 64 + mi * 16 + tr;
                int c0 = wn * 32 + ni * 8 + tc;
                SE[c0 * LD + r0]           = acc[mi][ni][0];
                SE[(c0 + 1) * LD + r0]     = acc[mi][ni][1];
                SE[c0 * LD + r0 + 8]       = acc[mi][ni][2];
                SE[(c0 + 1) * LD + r0 + 8] = acc[mi][ni][3];
            }
        __syncthreads();
#pragma unroll
        for (int i = 0; i < 16; i++) {
            int e = tid + i * NTHR;           // 0..4095 float4s
            int row = e >> 5;
            int c4 = (e & 31) * 4;
            float4 v = *reinterpret_cast<float4*>(&SE[row * LD + c4]);
            v.x *= alpha; v.y *= alpha; v.z *= alpha; v.w *= alpha;
            size_t o = (size_t)z * sC + (size_t)(n0 + row) * ldc + m0 + c4;
            if (Cf) *reinterpret_cast<float4*>(Cf + o) = v;
            if (Ch) {
                *reinterpret_cast<uint2*>(Ch + o) =
                    make_uint2(pack2(__float2half_rn(v.x), __float2half_rn(v.y)),
                               pack2(__float2half_rn(v.z), __float2half_rn(v.w)));
            }
        }
    }
}

// ---------------- host-side launcher ----------------
static void launch_gemm(bool trans,
                        const h16* A, size_t sA,
                        const h16* B, size_t sB,
                        float* Cf, h16* Ch, size_t sC,
                        int M, int N, int K, int ldc, float alpha,
                        const float* bias, int batch) {
    dim3 grid(N / BN, M / BM, batch);
    if (trans)
        gemm_mma<true><<<grid, NTHR, GSMEM_TR>>>(A, sA, B, sB, Cf, Ch, sC,
                                                 M, N, K, ldc, alpha, bias);
    else
        gemm_mma<false><<<grid, NTHR, GSMEM_NT>>>(A, sA, B, sB, Cf, Ch, sC,
                                                  M, N, K, ldc, alpha, bias);
}

#define SYM(var, sym)                                   \
    do {                                                \
        void* _p = nullptr;                             \
        cudaGetSymbolAddress(&_p, sym);                 \
        var = (decltype(var))_p;                        \
    } while (0)

extern "C" void kernel_launch(void* const* d_in, const int* in_sizes, int n_in,
                              void* d_out, int out_size) {
    const int*   input_text = (const int*)d_in[0];
    const float* target     = (const float*)d_in[1];
    const float* embed      = (const float*)d_in[2];
    const float* in_proj_w  = (const float*)d_in[3];
    const float* out_w      = (const float*)d_in[4];
    const float* out_b      = (const float*)d_in[5];
    const float* lin_w      = (const float*)d_in[6];
    const float* lin_b      = (const float*)d_in[7];
    float*       logits     = (float*)d_out;

    cudaFuncSetAttribute(gemm_mma<false>,
                         cudaFuncAttributeMaxDynamicSharedMemorySize, GSMEM_NT);
    cudaFuncSetAttribute(gemm_mma<true>,
                         cudaFuncAttributeMaxDynamicSharedMemorySize, GSMEM_TR);

    h16 *x, *T, *q, *p, *o, *k, *vT, *lin, *w, *wo;
    float* sc;
    SYM(x, g_x);   SYM(T, g_T);   SYM(q, g_q);   SYM(p, g_p);   SYM(o, g_o);
    SYM(k, g_k);   SYM(vT, g_vT); SYM(lin, g_lin);
    SYM(w, g_w);   SYM(wo, g_wo);
    SYM(sc, g_scores);

    gather_h<<<MTOT, 256>>>(input_text, embed, x);              // launch 1
    conv_h<<<4096, 256>>>(target, T, (size_t)MTOT * EDIM / 4);  // launch 2

    const size_t EE = (size_t)EDIM * EDIM;

    for (int l = 0; l < NL; l++) {
        conv_h<<<3072, 256>>>(in_proj_w + (size_t)l * 3 * EE, w, 3 * EE / 4);  // 3

        // q = (x @ Wq^T) * SCALE      <- 4th launch: profiled GEMM
        launch_gemm(false, x, 0, w, 0,
                    nullptr, q, 0,
                    MTOT, EDIM, EDIM, EDIM, SCALE_Q, nullptr, 1);

        conv_h<<<1024, 256>>>(out_w + (size_t)l * EE, wo, EE / 4);

        // k = target @ Wk^T
        launch_gemm(false, T, 0, w + EE, 0,
                    nullptr, k, 0,
                    MTOT, EDIM, EDIM, EDIM, 1.f, nullptr, 1);
        // vT[b] = (target_b @ Wv^T)^T  (transposed store)
        launch_gemm(true, T, (size_t)SKV * EDIM, w + 2 * EE, 0,
                    nullptr, vT, (size_t)EDIM * SKV,
                    SKV, EDIM, EDIM, SKV, 1.f, nullptr, NB);
        // scores[b] = q_b @ k_b^T      (fp32 out)
        launch_gemm(false, q, (size_t)SQ * EDIM, k, (size_t)SKV * EDIM,
                    sc, nullptr, (size_t)SQ * SKV,
                    SQ, SKV, EDIM, SKV, 1.f, nullptr, NB);
        softmax_h<<<NB * SQ, 256>>>(sc, p);
        // o[b] = attn_b @ vT_b^T
        launch_gemm(false, p, (size_t)SQ * SKV, vT, (size_t)EDIM * SKV,
                    nullptr, o, (size_t)SQ * EDIM,
                    SQ, EDIM, SKV, EDIM, 1.f, nullptr, NB);
        // x = o @ out_w^T + out_b
        launch_gemm(false, o, 0, wo, 0,
                    nullptr, x, 0,
                    MTOT, EDIM, EDIM, EDIM, 1.f, out_b + (size_t)l * EDIM, 1);
    }

    // logits = x @ lin_w^T + lin_b     (fp32 out)
    conv_h<<<8192, 256>>>(lin_w, lin, (size_t)VOC * EDIM / 4);
    launch_gemm(false, x, 0, lin, 0,
                logits, nullptr, 0,
                MTOT, VOC, EDIM, VOC, 1.f, lin_b, 1);
}

// round 16
// speedup vs baseline: 1.2144x; 1.0599x over previous
#include <cuda_runtime.h>
#include <cuda_fp16.h>
#include <cstdint>

typedef __half h16;

// ---------------- problem constants ----------------
#define NB    8
#define SQ    1024
#define SKV   1024
#define EDIM  1024
#define VOC   32000
#define NL    6
#define MTOT  (NB * SQ)        // 8192
#define EE    (EDIM * EDIM)
#define SCALE_Q 0.125f

// ---------------- device scratch ----------------
__device__ __align__(16) h16  g_x  [MTOT * EDIM];
__device__ __align__(16) h16  g_T  [MTOT * EDIM];
__device__ __align__(16) h16  g_q  [MTOT * EDIM];
__device__ __align__(16) h16  g_p  [NB * SQ * SKV];
__device__ __align__(16) h16  g_o  [MTOT * EDIM];
__device__ __align__(16) h16  g_k_all [NL * MTOT * EDIM];   // 96 MB
__device__ __align__(16) h16  g_vT_all[NL * MTOT * EDIM];   // 96 MB
__device__ __align__(16) h16  g_lin[VOC * EDIM];
__device__ __align__(16) h16  g_w_all [NL * 3 * EE];
__device__ __align__(16) h16  g_wo_all[NL * EE];
__device__ float g_scores[NB * SQ * SKV];

// ---------------- helpers ----------------
__device__ __forceinline__ uint32_t pack2(h16 a, h16 b) {
    __half2 p = __halves2half2(a, b);
    return *reinterpret_cast<uint32_t*>(&p);
}

__global__ void conv_h(const float* __restrict__ src, h16* __restrict__ h, size_t n4) {
    size_t stride = (size_t)gridDim.x * blockDim.x;
    for (size_t i = (size_t)blockIdx.x * blockDim.x + threadIdx.x; i < n4; i += stride) {
        float4 v = reinterpret_cast<const float4*>(src)[i];
        reinterpret_cast<uint2*>(h)[i] =
            make_uint2(pack2(__float2half_rn(v.x), __float2half_rn(v.y)),
                       pack2(__float2half_rn(v.z), __float2half_rn(v.w)));
    }
}

__global__ void gather_h(const int* __restrict__ idx, const float* __restrict__ embed,
                         h16* __restrict__ x) {
    int row = blockIdx.x;
    int tok = idx[row];
    const float4* src = reinterpret_cast<const float4*>(embed + (size_t)tok * EDIM);
    float4 v = src[threadIdx.x];
    reinterpret_cast<uint2*>(x + (size_t)row * EDIM)[threadIdx.x] =
        make_uint2(pack2(__float2half_rn(v.x), __float2half_rn(v.y)),
                   pack2(__float2half_rn(v.z), __float2half_rn(v.w)));
}

__global__ void softmax_h(const float* __restrict__ S, h16* __restrict__ P) {
    int row = blockIdx.x;
    int t = threadIdx.x;
    int lane = t & 31, w = t >> 5;
    float4 v = reinterpret_cast<const float4*>(S + (size_t)row * SKV)[t];

    float m = fmaxf(fmaxf(v.x, v.y), fmaxf(v.z, v.w));
#pragma unroll
    for (int off = 16; off > 0; off >>= 1)
        m = fmaxf(m, __shfl_xor_sync(0xFFFFFFFFu, m, off));
    __shared__ float red[8];
    if (lane == 0) red[w] = m;
    __syncthreads();
    float mx = red[0];
#pragma unroll
    for (int i = 1; i < 8; i++) mx = fmaxf(mx, red[i]);

    v.x = __expf(v.x - mx); v.y = __expf(v.y - mx);
    v.z = __expf(v.z - mx); v.w = __expf(v.w - mx);
    float s = v.x + v.y + v.z + v.w;
#pragma unroll
    for (int off = 16; off > 0; off >>= 1)
        s += __shfl_xor_sync(0xFFFFFFFFu, s, off);
    __shared__ float red2[8];
    if (lane == 0) red2[w] = s;
    __syncthreads();
    float tot = red2[0];
#pragma unroll
    for (int i = 1; i < 8; i++) tot += red2[i];
    float inv = 1.f / tot;

    reinterpret_cast<uint2*>(P + (size_t)row * SKV)[t] =
        make_uint2(pack2(__float2half_rn(v.x * inv), __float2half_rn(v.y * inv)),
                   pack2(__float2half_rn(v.z * inv), __float2half_rn(v.w * inv)));
}

// ---------------- GEMM core: 128x128x64 tile, 256 threads, 2 CTAs/SM ----------------
#define BK        64
#define BM        128
#define BN        128
#define NTHR      256
#define LDROW     144
#define A_BYTES   (BM * LDROW)               // 18432
#define B_BYTES   (BN * LDROW)               // 18432
#define STAGE_B   (A_BYTES + B_BYTES)        // 36864
#define GSMEM     (2 * STAGE_B)              // 73728 (>= staged epilogue 67584)
#define GROUP_Y   8

__device__ __forceinline__ uint32_t smem_u32(const void* p) {
    uint32_t a;
    asm("{ .reg .u64 t; cvta.to.shared.u64 t, %1; cvt.u32.u64 %0, t; }" : "=r"(a) : "l"(p));
    return a;
}

__device__ __forceinline__ void ldm_x4(uint32_t& r0, uint32_t& r1, uint32_t& r2,
                                       uint32_t& r3, uint32_t addr) {
    asm volatile("ldmatrix.sync.aligned.m8n8.x4.shared.b16 {%0,%1,%2,%3}, [%4];"
                 : "=r"(r0), "=r"(r1), "=r"(r2), "=r"(r3) : "r"(addr));
}

__device__ __forceinline__ void mma16816(float* c, const uint32_t* a, const uint32_t* b) {
    asm volatile(
        "mma.sync.aligned.m16n8k16.row.col.f32.f16.f16.f32 "
        "{%0,%1,%2,%3}, {%4,%5,%6,%7}, {%8,%9}, {%0,%1,%2,%3};"
        : "+f"(c[0]), "+f"(c[1]), "+f"(c[2]), "+f"(c[3])
        : "r"(a[0]), "r"(a[1]), "r"(a[2]), "r"(a[3]), "r"(b[0]), "r"(b[1]));
}

__device__ __forceinline__ void fill_stage(uint32_t sbase,
    const h16* __restrict__ A0, const h16* __restrict__ B0,
    int K, int k0, int tid)
{
#pragma unroll
    for (int j = 0; j < 4; j++) {
        int e = tid + j * NTHR;
        int row = e >> 3, c = e & 7;
        uint32_t dst = sbase + row * LDROW + c * 16;
        uint64_t src = __cvta_generic_to_global((const void*)(A0 + (size_t)row * K + k0 + c * 8));
        asm volatile("cp.async.cg.shared.global [%0], [%1], 16;" :: "r"(dst), "l"(src));
    }
#pragma unroll
    for (int j = 0; j < 4; j++) {
        int e = tid + j * NTHR;
        int row = e >> 3, c = e & 7;
        uint32_t dst = sbase + A_BYTES + row * LDROW + c * 16;
        uint64_t src = __cvta_generic_to_global((const void*)(B0 + (size_t)row * K + k0 + c * 8));
        asm volatile("cp.async.cg.shared.global [%0], [%1], 16;" :: "r"(dst), "l"(src));
    }
    asm volatile("cp.async.commit_group;" ::: "memory");
}

// Core mainloop + epilogue. trans is a runtime flag (epilogue only).
// A0/B0 are tile bases (A + m0*K, B + n0*K); Cf/Ch already offset to the matrix base.
__device__ __forceinline__ void gemm_core(
    const h16* __restrict__ A0, const h16* __restrict__ B0,
    float* __restrict__ Cf, h16* __restrict__ Ch,
    int K, int ldc, float alpha, const float* __restrict__ bias,
    int m0, int n0, bool trans, char* smem)
{
    const uint32_t sb = smem_u32(smem);
    const int tid  = threadIdx.x;
    const int wid  = tid >> 5;
    const int lane = tid & 31;
    const int wm = wid >> 2;                  // 0..1
    const int wn = wid & 3;                   // 0..3

    const uint32_t a_base = (uint32_t)((wm * 64 + (lane & 15)) * LDROW + (lane >> 4) * 16);
    const uint32_t b_base = (uint32_t)((wn * 32 + (lane >> 4) * 8 + (lane & 7)) * LDROW
                                       + ((lane >> 3) & 1) * 16);

    float acc[4][4][4];
#pragma unroll
    for (int i = 0; i < 4; i++)
#pragma unroll
        for (int j = 0; j < 4; j++)
#pragma unroll
            for (int r = 0; r < 4; r++) acc[i][j][r] = 0.f;

    const int KT = K / BK;

    fill_stage(sb, A0, B0, K, 0, tid);        // prefill stage 0

    int stage = 0;
    for (int kt = 0; kt < KT; kt++) {
        asm volatile("cp.async.wait_group 0;" ::: "memory");
        __syncthreads();

        int f = kt + 1;
        if (f < KT)
            fill_stage(sb + (f & 1) * STAGE_B, A0, B0, K, f * BK, tid);

        const uint32_t sA_ = sb + stage * STAGE_B;
        const uint32_t sB_ = sA_ + A_BYTES;

#pragma unroll
        for (int ks = 0; ks < 4; ks++) {
            const uint32_t ko = ks * 32;
            uint32_t ah[4][4], bh[4][2];
#pragma unroll
            for (int mi = 0; mi < 4; mi++) {
                uint32_t off = a_base + mi * 16 * LDROW + ko;
                ldm_x4(ah[mi][0], ah[mi][1], ah[mi][2], ah[mi][3], sA_ + off);
            }
#pragma unroll
            for (int p = 0; p < 2; p++) {
                uint32_t off = b_base + p * 16 * LDROW + ko;
                ldm_x4(bh[2 * p][0], bh[2 * p][1], bh[2 * p + 1][0], bh[2 * p + 1][1], sB_ + off);
            }
#pragma unroll
            for (int mi = 0; mi < 4; mi++)
#pragma unroll
                for (int ni = 0; ni < 4; ni++)
                    mma16816(acc[mi][ni], ah[mi], bh[ni]);
        }
        stage ^= 1;
    }

    const int tr = lane >> 2;
    const int tc = (lane & 3) * 2;

    if (!trans) {
        // direct global stores (fragment c-pairs contiguous)
#pragma unroll
        for (int mi = 0; mi < 4; mi++)
#pragma unroll
            for (int ni = 0; ni < 4; ni++) {
                int gr = m0 + wm * 64 + mi * 16 + tr;
                int gc = n0 + wn * 32 + ni * 8 + tc;
                float v0 = acc[mi][ni][0] * alpha;
                float v1 = acc[mi][ni][1] * alpha;
                float v2 = acc[mi][ni][2] * alpha;
                float v3 = acc[mi][ni][3] * alpha;
                if (bias) {
                    float b0 = bias[gc], b1 = bias[gc + 1];
                    v0 += b0; v1 += b1; v2 += b0; v3 += b1;
                }
                size_t o0 = (size_t)gr * ldc + gc;
                size_t o1 = o0 + (size_t)8 * ldc;
                if (Cf) {
                    *reinterpret_cast<float2*>(Cf + o0) = make_float2(v0, v1);
                    *reinterpret_cast<float2*>(Cf + o1) = make_float2(v2, v3);
                }
                if (Ch) {
                    *reinterpret_cast<uint32_t*>(Ch + o0) =
                        pack2(__float2half_rn(v0), __float2half_rn(v1));
                    *reinterpret_cast<uint32_t*>(Ch + o1) =
                        pack2(__float2half_rn(v2), __float2half_rn(v3));
                }
            }
    } else {
        // staged transposed epilogue
        __syncthreads();
        const int LD = 132;
        float* SE = reinterpret_cast<float*>(smem);
#pragma unroll
        for (int mi = 0; mi < 4; mi++)
#pragma unroll
            for (int ni = 0; ni < 4; ni++) {
                int r0 = wm * 64 + mi * 16 + tr;
                int c0 = wn * 32 + ni * 8 + tc;
                SE[c0 * LD + r0]           = acc[mi][ni][0];
                SE[(c0 + 1) * LD + r0]     = acc[mi][ni][1];
                SE[c0 * LD + r0 + 8]       = acc[mi][ni][2];
                SE[(c0 + 1) * LD + r0 + 8] = acc[mi][ni][3];
            }
        __syncthreads();
#pragma unroll
        for (int i = 0; i < 16; i++) {
            int e = tid + i * NTHR;
            int row = e >> 5;
            int c4 = (e & 31) * 4;
            float4 v = *reinterpret_cast<float4*>(&SE[row * LD + c4]);
            v.x *= alpha; v.y *= alpha; v.z *= alpha; v.w *= alpha;
            size_t o = (size_t)(n0 + row) * ldc + m0 + c4;
            if (Ch) {
                *reinterpret_cast<uint2*>(Ch + o) =
                    make_uint2(pack2(__float2half_rn(v.x), __float2half_rn(v.y)),
                               pack2(__float2half_rn(v.z), __float2half_rn(v.w)));
            }
        }
    }
}

// ---------------- generic non-trans GEMM (batched, grouped raster) ----------------
__global__ void __launch_bounds__(NTHR, 2)
gemm_g(const h16* __restrict__ A, size_t sA,
       const h16* __restrict__ B, size_t sB,
       float* __restrict__ Cf, h16* __restrict__ Ch, size_t sC,
       int K, int ldc, float alpha, const float* __restrict__ bias)
{
    extern __shared__ __align__(128) char smem[];
    const int z = blockIdx.z;

    int lin = blockIdx.y * gridDim.x + blockIdx.x;
    int gsz = GROUP_Y * gridDim.x;
    int grp = lin / gsz, rem = lin % gsz;
    int span = min(GROUP_Y, (int)gridDim.y - grp * GROUP_Y);
    int by = grp * GROUP_Y + rem % span;
    int bx = rem / span;
    const int m0 = by * BM;
    const int n0 = bx * BN;

    gemm_core(A + (size_t)z * sA + (size_t)m0 * K,
              B + (size_t)z * sB + (size_t)n0 * K,
              Cf ? Cf + (size_t)z * sC : nullptr,
              Ch ? Ch + (size_t)z * sC : nullptr,
              K, ldc, alpha, bias, m0, n0, false, smem);
}

// ---------------- fused q0 + all-layer k + all-layer vT ----------------
// grid (8, 64, 13): z=0 -> q0 ; z=1..6 -> k_{z-1} ; z=7..12 -> vT_{z-7}
__global__ void __launch_bounds__(NTHR, 2)
qkv_fused(const h16* __restrict__ x, const h16* __restrict__ T,
          const h16* __restrict__ w_all,
          h16* __restrict__ q, h16* __restrict__ k_all, h16* __restrict__ vT_all)
{
    extern __shared__ __align__(128) char smem[];
    const int z  = blockIdx.z;
    const int bx = blockIdx.x;
    const int by = blockIdx.y;
    const size_t SZ = (size_t)MTOT * EDIM;

    const h16* A0;
    const h16* B0;
    h16* Ch;
    int m0, n0, ldc;
    float alpha;
    bool trans;

    if (z == 0) {
        m0 = by * BM; n0 = bx * BN;
        A0 = x + (size_t)m0 * EDIM;
        B0 = w_all + (size_t)n0 * EDIM;              // Wq, layer 0
        Ch = q; ldc = EDIM; alpha = SCALE_Q; trans = false;
    } else if (z <= NL) {
        int l = z - 1;
        m0 = by * BM; n0 = bx * BN;
        A0 = T + (size_t)m0 * EDIM;
        B0 = w_all + (size_t)l * 3 * EE + EE + (size_t)n0 * EDIM;   // Wk
        Ch = k_all + (size_t)l * SZ; ldc = EDIM; alpha = 1.f; trans = false;
    } else {
        int l = z - 1 - NL;
        int bt = by >> 3, yy = by & 7;
        m0 = yy * BM; n0 = bx * BN;
        A0 = T + (size_t)bt * SQ * EDIM + (size_t)m0 * EDIM;
        B0 = w_all + (size_t)l * 3 * EE + 2 * EE + (size_t)n0 * EDIM;  // Wv
        Ch = vT_all + (size_t)l * SZ + (size_t)bt * EDIM * SKV;
        ldc = SKV; alpha = 1.f; trans = true;
    }

    gemm_core(A0, B0, nullptr, Ch, EDIM, ldc, alpha, nullptr, m0, n0, trans, smem);
}

// ---------------- host-side launcher ----------------
static void launch_gemm(const h16* A, size_t sA,
                        const h16* B, size_t sB,
                        float* Cf, h16* Ch, size_t sC,
                        int M, int N, int K, int ldc, float alpha,
                        const float* bias, int batch) {
    dim3 grid(N / BN, M / BM, batch);
    gemm_g<<<grid, NTHR, GSMEM>>>(A, sA, B, sB, Cf, Ch, sC, K, ldc, alpha, bias);
}

#define SYM(var, sym)                                   \
    do {                                                \
        void* _p = nullptr;                             \
        cudaGetSymbolAddress(&_p, sym);                 \
        var = (decltype(var))_p;                        \
    } while (0)

extern "C" void kernel_launch(void* const* d_in, const int* in_sizes, int n_in,
                              void* d_out, int out_size) {
    const int*   input_text = (const int*)d_in[0];
    const float* target     = (const float*)d_in[1];
    const float* embed      = (const float*)d_in[2];
    const float* in_proj_w  = (const float*)d_in[3];
    const float* out_w      = (const float*)d_in[4];
    const float* out_b      = (const float*)d_in[5];
    const float* lin_w      = (const float*)d_in[6];
    const float* lin_b      = (const float*)d_in[7];
    float*       logits     = (float*)d_out;

    cudaFuncSetAttribute(gemm_g,    cudaFuncAttributeMaxDynamicSharedMemorySize, GSMEM);
    cudaFuncSetAttribute(qkv_fused, cudaFuncAttributeMaxDynamicSharedMemorySize, GSMEM);

    h16 *x, *T, *q, *p, *o, *k_all, *vT_all, *lin, *w_all, *wo_all;
    float* sc;
    SYM(x, g_x);   SYM(T, g_T);   SYM(q, g_q);   SYM(p, g_p);   SYM(o, g_o);
    SYM(k_all, g_k_all);   SYM(vT_all, g_vT_all); SYM(lin, g_lin);
    SYM(w_all, g_w_all);   SYM(wo_all, g_wo_all);
    SYM(sc, g_scores);

    const size_t SZ = (size_t)MTOT * EDIM;

    gather_h<<<MTOT, 256>>>(input_text, embed, x);                       // 1
    conv_h<<<4096, 256>>>(target, T, SZ / 4);                            // 2
    conv_h<<<8192, 256>>>(in_proj_w, w_all, (size_t)NL * 3 * EE / 4);    // 3
    conv_h<<<3072, 256>>>(out_w, wo_all, (size_t)NL * EE / 4);           // 4

    // 5: fused q0 + all k_l + all vT_l  (6656 CTAs, one launch)
    {
        dim3 grid(8, 64, 1 + 2 * NL);
        qkv_fused<<<grid, NTHR, GSMEM>>>(x, T, w_all, q, k_all, vT_all);
    }

    for (int l = 0; l < NL; l++) {
        // scores[b] = q_b @ k_b^T   (fp32)   <- launch 6 (l=0): profiled
        launch_gemm(q, (size_t)SQ * EDIM, k_all + (size_t)l * SZ, (size_t)SKV * EDIM,
                    sc, nullptr, (size_t)SQ * SKV,
                    SQ, SKV, EDIM, SKV, 1.f, nullptr, NB);
        softmax_h<<<NB * SQ, 256>>>(sc, p);
        // o[b] = attn_b @ vT_b^T
        launch_gemm(p, (size_t)SQ * SKV, vT_all + (size_t)l * SZ, (size_t)EDIM * SKV,
                    nullptr, o, (size_t)SQ * EDIM,
                    SQ, EDIM, SKV, EDIM, 1.f, nullptr, NB);
        // x = o @ out_w^T + out_b
        launch_gemm(o, 0, wo_all + (size_t)l * EE, 0,
                    nullptr, x, 0,
                    MTOT, EDIM, EDIM, EDIM, 1.f, out_b + (size_t)l * EDIM, 1);
        // q_{l+1} = (x @ Wq_{l+1}^T) * SCALE
        if (l + 1 < NL)
            launch_gemm(x, 0, w_all + (size_t)(l + 1) * 3 * EE, 0,
                        nullptr, q, 0,
                        MTOT, EDIM, EDIM, EDIM, SCALE_Q, nullptr, 1);
    }

    // logits = x @ lin_w^T + lin_b  (fp32 out)
    conv_h<<<8192, 256>>>(lin_w, lin, (size_t)VOC * EDIM / 4);
    launch_gemm(x, 0, lin, 0,
                logits, nullptr, 0,
                MTOT, VOC, EDIM, VOC, 1.f, lin_b, 1);
}

// round 17
// speedup vs baseline: 1.2490x; 1.0285x over previous
#include <cuda_runtime.h>
#include <cuda_fp16.h>
#include <cstdint>

typedef __half h16;

// ---------------- problem constants ----------------
#define NB    8
#define SQ    1024
#define SKV   1024
#define EDIM  1024
#define VOC   32000
#define NL    6
#define MTOT  (NB * SQ)        // 8192
#define EE    (EDIM * EDIM)
#define SCALE_Q 0.125f

// ---------------- device scratch ----------------
__device__ __align__(16) h16  g_x  [MTOT * EDIM];
__device__ __align__(16) h16  g_T  [MTOT * EDIM];
__device__ __align__(16) h16  g_q  [MTOT * EDIM];
__device__ __align__(16) h16  g_p  [NB * SQ * SKV];
__device__ __align__(16) h16  g_o  [MTOT * EDIM];
__device__ __align__(16) h16  g_k_all [NL * MTOT * EDIM];
__device__ __align__(16) h16  g_vT_all[NL * MTOT * EDIM];
__device__ __align__(16) h16  g_lin[VOC * EDIM];
__device__ __align__(16) h16  g_w_all [NL * 3 * EE];
__device__ __align__(16) h16  g_wo_all[NL * EE];
__device__ float g_scores[NB * SQ * SKV];

// ---------------- helpers ----------------
__device__ __forceinline__ uint32_t pack2(h16 a, h16 b) {
    __half2 p = __halves2half2(a, b);
    return *reinterpret_cast<uint32_t*>(&p);
}

__global__ void conv_h(const float* __restrict__ src, h16* __restrict__ h, size_t n4) {
    size_t stride = (size_t)gridDim.x * blockDim.x;
    for (size_t i = (size_t)blockIdx.x * blockDim.x + threadIdx.x; i < n4; i += stride) {
        float4 v = reinterpret_cast<const float4*>(src)[i];
        reinterpret_cast<uint2*>(h)[i] =
            make_uint2(pack2(__float2half_rn(v.x), __float2half_rn(v.y)),
                       pack2(__float2half_rn(v.z), __float2half_rn(v.w)));
    }
}

__global__ void gather_h(const int* __restrict__ idx, const float* __restrict__ embed,
                         h16* __restrict__ x) {
    int row = blockIdx.x;
    int tok = idx[row];
    const float4* src = reinterpret_cast<const float4*>(embed + (size_t)tok * EDIM);
    float4 v = src[threadIdx.x];
    reinterpret_cast<uint2*>(x + (size_t)row * EDIM)[threadIdx.x] =
        make_uint2(pack2(__float2half_rn(v.x), __float2half_rn(v.y)),
                   pack2(__float2half_rn(v.z), __float2half_rn(v.w)));
}

__global__ void softmax_h(const float* __restrict__ S, h16* __restrict__ P) {
    int row = blockIdx.x;
    int t = threadIdx.x;
    int lane = t & 31, w = t >> 5;
    float4 v = reinterpret_cast<const float4*>(S + (size_t)row * SKV)[t];

    float m = fmaxf(fmaxf(v.x, v.y), fmaxf(v.z, v.w));
#pragma unroll
    for (int off = 16; off > 0; off >>= 1)
        m = fmaxf(m, __shfl_xor_sync(0xFFFFFFFFu, m, off));
    __shared__ float red[8];
    if (lane == 0) red[w] = m;
    __syncthreads();
    float mx = red[0];
#pragma unroll
    for (int i = 1; i < 8; i++) mx = fmaxf(mx, red[i]);

    v.x = __expf(v.x - mx); v.y = __expf(v.y - mx);
    v.z = __expf(v.z - mx); v.w = __expf(v.w - mx);
    float s = v.x + v.y + v.z + v.w;
#pragma unroll
    for (int off = 16; off > 0; off >>= 1)
        s += __shfl_xor_sync(0xFFFFFFFFu, s, off);
    __shared__ float red2[8];
    if (lane == 0) red2[w] = s;
    __syncthreads();
    float tot = red2[0];
#pragma unroll
    for (int i = 1; i < 8; i++) tot += red2[i];
    float inv = 1.f / tot;

    reinterpret_cast<uint2*>(P + (size_t)row * SKV)[t] =
        make_uint2(pack2(__float2half_rn(v.x * inv), __float2half_rn(v.y * inv)),
                   pack2(__float2half_rn(v.z * inv), __float2half_rn(v.w * inv)));
}

// ---------------- GEMM core: 128x128x64 tile, 128 threads (4 warps 2x2), 3 CTAs/SM ----------------
// Warp tile 64x64 -> A/B each read only 2x from SMEM: crossbar traffic/iter
// drops 133KB -> 101KB, tensor ceiling ~65%.
#define BK        64
#define BM        128
#define BN        128
#define NTHR      128
#define LDROW     144
#define A_BYTES   (BM * LDROW)               // 18432
#define B_BYTES   (BN * LDROW)               // 18432
#define STAGE_B   (A_BYTES + B_BYTES)        // 36864
#define GSMEM     (2 * STAGE_B)              // 73728 (>= staged epilogue 67584); x3 CTAs = 221KB
#define GROUP_Y   8

__device__ __forceinline__ uint32_t smem_u32(const void* p) {
    uint32_t a;
    asm("{ .reg .u64 t; cvta.to.shared.u64 t, %1; cvt.u32.u64 %0, t; }" : "=r"(a) : "l"(p));
    return a;
}

__device__ __forceinline__ void ldm_x4(uint32_t& r0, uint32_t& r1, uint32_t& r2,
                                       uint32_t& r3, uint32_t addr) {
    asm volatile("ldmatrix.sync.aligned.m8n8.x4.shared.b16 {%0,%1,%2,%3}, [%4];"
                 : "=r"(r0), "=r"(r1), "=r"(r2), "=r"(r3) : "r"(addr));
}

__device__ __forceinline__ void mma16816(float* c, const uint32_t* a, const uint32_t* b) {
    asm volatile(
        "mma.sync.aligned.m16n8k16.row.col.f32.f16.f16.f32 "
        "{%0,%1,%2,%3}, {%4,%5,%6,%7}, {%8,%9}, {%0,%1,%2,%3};"
        : "+f"(c[0]), "+f"(c[1]), "+f"(c[2]), "+f"(c[3])
        : "r"(a[0]), "r"(a[1]), "r"(a[2]), "r"(a[3]), "r"(b[0]), "r"(b[1]));
}

__device__ __forceinline__ void fill_stage(uint32_t sbase,
    const h16* __restrict__ A0, const h16* __restrict__ B0,
    int K, int k0, int tid)
{
    // A: 128 rows x 8 chunks of 16B = 1024 tasks, 128 threads -> 8 rounds
#pragma unroll
    for (int j = 0; j < 8; j++) {
        int e = tid + j * NTHR;
        int row = e >> 3, c = e & 7;
        uint32_t dst = sbase + row * LDROW + c * 16;
        uint64_t src = __cvta_generic_to_global((const void*)(A0 + (size_t)row * K + k0 + c * 8));
        asm volatile("cp.async.cg.shared.global [%0], [%1], 16;" :: "r"(dst), "l"(src));
    }
#pragma unroll
    for (int j = 0; j < 8; j++) {
        int e = tid + j * NTHR;
        int row = e >> 3, c = e & 7;
        uint32_t dst = sbase + A_BYTES + row * LDROW + c * 16;
        uint64_t src = __cvta_generic_to_global((const void*)(B0 + (size_t)row * K + k0 + c * 8));
        asm volatile("cp.async.cg.shared.global [%0], [%1], 16;" :: "r"(dst), "l"(src));
    }
    asm volatile("cp.async.commit_group;" ::: "memory");
}

// Core mainloop + epilogue. trans is a runtime flag (epilogue only).
__device__ __forceinline__ void gemm_core(
    const h16* __restrict__ A0, const h16* __restrict__ B0,
    float* __restrict__ Cf, h16* __restrict__ Ch,
    int K, int ldc, float alpha, const float* __restrict__ bias,
    int m0, int n0, bool trans, char* smem)
{
    const uint32_t sb = smem_u32(smem);
    const int tid  = threadIdx.x;
    const int wid  = tid >> 5;
    const int lane = tid & 31;
    const int wm = wid >> 1;                  // 0..1 : 64-row block
    const int wn = wid & 1;                   // 0..1 : 64-col block

    const uint32_t a_base = (uint32_t)((wm * 64 + (lane & 15)) * LDROW + (lane >> 4) * 16);
    const uint32_t b_base = (uint32_t)((wn * 64 + (lane >> 4) * 8 + (lane & 7)) * LDROW
                                       + ((lane >> 3) & 1) * 16);

    float acc[4][8][4];
#pragma unroll
    for (int i = 0; i < 4; i++)
#pragma unroll
        for (int j = 0; j < 8; j++)
#pragma unroll
            for (int r = 0; r < 4; r++) acc[i][j][r] = 0.f;

    const int KT = K / BK;

    fill_stage(sb, A0, B0, K, 0, tid);        // prefill stage 0

    int stage = 0;
    for (int kt = 0; kt < KT; kt++) {
        asm volatile("cp.async.wait_group 0;" ::: "memory");
        __syncthreads();

        int f = kt + 1;
        if (f < KT)
            fill_stage(sb + (f & 1) * STAGE_B, A0, B0, K, f * BK, tid);

        const uint32_t sA_ = sb + stage * STAGE_B;
        const uint32_t sB_ = sA_ + A_BYTES;

#pragma unroll
        for (int ks = 0; ks < 4; ks++) {      // 4 k-steps of 16
            const uint32_t ko = ks * 32;
            uint32_t ah[4][4], bh[8][2];
#pragma unroll
            for (int mi = 0; mi < 4; mi++) {
                uint32_t off = a_base + mi * 16 * LDROW + ko;
                ldm_x4(ah[mi][0], ah[mi][1], ah[mi][2], ah[mi][3], sA_ + off);
            }
#pragma unroll
            for (int p = 0; p < 4; p++) {     // each x4 covers two n8 blocks
                uint32_t off = b_base + p * 16 * LDROW + ko;
                ldm_x4(bh[2 * p][0], bh[2 * p][1], bh[2 * p + 1][0], bh[2 * p + 1][1], sB_ + off);
            }
#pragma unroll
            for (int mi = 0; mi < 4; mi++)
#pragma unroll
                for (int ni = 0; ni < 8; ni++)
                    mma16816(acc[mi][ni], ah[mi], bh[ni]);
        }
        stage ^= 1;
    }

    const int tr = lane >> 2;
    const int tc = (lane & 3) * 2;

    if (!trans) {
        // direct global stores (fragment c-pairs contiguous)
#pragma unroll
        for (int mi = 0; mi < 4; mi++)
#pragma unroll
            for (int ni = 0; ni < 8; ni++) {
                int gr = m0 + wm * 64 + mi * 16 + tr;
                int gc = n0 + wn * 64 + ni * 8 + tc;
                float v0 = acc[mi][ni][0] * alpha;
                float v1 = acc[mi][ni][1] * alpha;
                float v2 = acc[mi][ni][2] * alpha;
                float v3 = acc[mi][ni][3] * alpha;
                if (bias) {
                    float b0 = bias[gc], b1 = bias[gc + 1];
                    v0 += b0; v1 += b1; v2 += b0; v3 += b1;
                }
                size_t o0 = (size_t)gr * ldc + gc;
                size_t o1 = o0 + (size_t)8 * ldc;
                if (Cf) {
                    *reinterpret_cast<float2*>(Cf + o0) = make_float2(v0, v1);
                    *reinterpret_cast<float2*>(Cf + o1) = make_float2(v2, v3);
                }
                if (Ch) {
                    *reinterpret_cast<uint32_t*>(Ch + o0) =
                        pack2(__float2half_rn(v0), __float2half_rn(v1));
                    *reinterpret_cast<uint32_t*>(Ch + o1) =
                        pack2(__float2half_rn(v2), __float2half_rn(v3));
                }
            }
    } else {
        // staged transposed epilogue
        __syncthreads();
        const int LD = 132;
        float* SE = reinterpret_cast<float*>(smem);
#pragma unroll
        for (int mi = 0; mi < 4; mi++)
#pragma unroll
            for (int ni = 0; ni < 8; ni++) {
                int r0 = wm * 64 + mi * 16 + tr;
                int c0 = wn * 64 + ni * 8 + tc;
                SE[c0 * LD + r0]           = acc[mi][ni][0];
                SE[(c0 + 1) * LD + r0]     = acc[mi][ni][1];
                SE[c0 * LD + r0 + 8]       = acc[mi][ni][2];
                SE[(c0 + 1) * LD + r0 + 8] = acc[mi][ni][3];
            }
        __syncthreads();
#pragma unroll
        for (int i = 0; i < 32; i++) {
            int e = tid + i * NTHR;           // 0..4095 float4s
            int row = e >> 5;
            int c4 = (e & 31) * 4;
            float4 v = *reinterpret_cast<float4*>(&SE[row * LD + c4]);
            v.x *= alpha; v.y *= alpha; v.z *= alpha; v.w *= alpha;
            size_t o = (size_t)(n0 + row) * ldc + m0 + c4;
            if (Ch) {
                *reinterpret_cast<uint2*>(Ch + o) =
                    make_uint2(pack2(__float2half_rn(v.x), __float2half_rn(v.y)),
                               pack2(__float2half_rn(v.z), __float2half_rn(v.w)));
            }
        }
    }
}

// ---------------- generic non-trans GEMM (batched, grouped raster) ----------------
__global__ void __launch_bounds__(NTHR, 3)
gemm_g(const h16* __restrict__ A, size_t sA,
       const h16* __restrict__ B, size_t sB,
       float* __restrict__ Cf, h16* __restrict__ Ch, size_t sC,
       int K, int ldc, float alpha, const float* __restrict__ bias)
{
    extern __shared__ __align__(128) char smem[];
    const int z = blockIdx.z;

    int lin = blockIdx.y * gridDim.x + blockIdx.x;
    int gsz = GROUP_Y * gridDim.x;
    int grp = lin / gsz, rem = lin % gsz;
    int span = min(GROUP_Y, (int)gridDim.y - grp * GROUP_Y);
    int by = grp * GROUP_Y + rem % span;
    int bx = rem / span;
    const int m0 = by * BM;
    const int n0 = bx * BN;

    gemm_core(A + (size_t)z * sA + (size_t)m0 * K,
              B + (size_t)z * sB + (size_t)n0 * K,
              Cf ? Cf + (size_t)z * sC : nullptr,
              Ch ? Ch + (size_t)z * sC : nullptr,
              K, ldc, alpha, bias, m0, n0, false, smem);
}

// ---------------- fused q0 + all-layer k + all-layer vT ----------------
// grid (8, 64, 13): z=0 -> q0 ; z=1..6 -> k_{z-1} ; z=7..12 -> vT_{z-7}
__global__ void __launch_bounds__(NTHR, 3)
qkv_fused(const h16* __restrict__ x, const h16* __restrict__ T,
          const h16* __restrict__ w_all,
          h16* __restrict__ q, h16* __restrict__ k_all, h16* __restrict__ vT_all)
{
    extern __shared__ __align__(128) char smem[];
    const int z  = blockIdx.z;
    const int bx = blockIdx.x;
    const int by = blockIdx.y;
    const size_t SZ = (size_t)MTOT * EDIM;

    const h16* A0;
    const h16* B0;
    h16* Ch;
    int m0, n0, ldc;
    float alpha;
    bool trans;

    if (z == 0) {
        m0 = by * BM; n0 = bx * BN;
        A0 = x + (size_t)m0 * EDIM;
        B0 = w_all + (size_t)n0 * EDIM;              // Wq, layer 0
        Ch = q; ldc = EDIM; alpha = SCALE_Q; trans = false;
    } else if (z <= NL) {
        int l = z - 1;
        m0 = by * BM; n0 = bx * BN;
        A0 = T + (size_t)m0 * EDIM;
        B0 = w_all + (size_t)l * 3 * EE + EE + (size_t)n0 * EDIM;   // Wk
        Ch = k_all + (size_t)l * SZ; ldc = EDIM; alpha = 1.f; trans = false;
    } else {
        int l = z - 1 - NL;
        int bt = by >> 3, yy = by & 7;
        m0 = yy * BM; n0 = bx * BN;
        A0 = T + (size_t)bt * SQ * EDIM + (size_t)m0 * EDIM;
        B0 = w_all + (size_t)l * 3 * EE + 2 * EE + (size_t)n0 * EDIM;  // Wv
        Ch = vT_all + (size_t)l * SZ + (size_t)bt * EDIM * SKV;
        ldc = SKV; alpha = 1.f; trans = true;
    }

    gemm_core(A0, B0, nullptr, Ch, EDIM, ldc, alpha, nullptr, m0, n0, trans, smem);
}

// ---------------- host-side launcher ----------------
static void launch_gemm(const h16* A, size_t sA,
                        const h16* B, size_t sB,
                        float* Cf, h16* Ch, size_t sC,
                        int M, int N, int K, int ldc, float alpha,
                        const float* bias, int batch) {
    dim3 grid(N / BN, M / BM, batch);
    gemm_g<<<grid, NTHR, GSMEM>>>(A, sA, B, sB, Cf, Ch, sC, K, ldc, alpha, bias);
}

#define SYM(var, sym)                                   \
    do {                                                \
        void* _p = nullptr;                             \
        cudaGetSymbolAddress(&_p, sym);                 \
        var = (decltype(var))_p;                        \
    } while (0)

extern "C" void kernel_launch(void* const* d_in, const int* in_sizes, int n_in,
                              void* d_out, int out_size) {
    const int*   input_text = (const int*)d_in[0];
    const float* target     = (const float*)d_in[1];
    const float* embed      = (const float*)d_in[2];
    const float* in_proj_w  = (const float*)d_in[3];
    const float* out_w      = (const float*)d_in[4];
    const float* out_b      = (const float*)d_in[5];
    const float* lin_w      = (const float*)d_in[6];
    const float* lin_b      = (const float*)d_in[7];
    float*       logits     = (float*)d_out;

    cudaFuncSetAttribute(gemm_g,    cudaFuncAttributeMaxDynamicSharedMemorySize, GSMEM);
    cudaFuncSetAttribute(qkv_fused, cudaFuncAttributeMaxDynamicSharedMemorySize, GSMEM);

    h16 *x, *T, *q, *p, *o, *k_all, *vT_all, *lin, *w_all, *wo_all;
    float* sc;
    SYM(x, g_x);   SYM(T, g_T);   SYM(q, g_q);   SYM(p, g_p);   SYM(o, g_o);
    SYM(k_all, g_k_all);   SYM(vT_all, g_vT_all); SYM(lin, g_lin);
    SYM(w_all, g_w_all);   SYM(wo_all, g_wo_all);
    SYM(sc, g_scores);

    const size_t SZ = (size_t)MTOT * EDIM;

    gather_h<<<MTOT, 256>>>(input_text, embed, x);                       // 1
    conv_h<<<4096, 256>>>(target, T, SZ / 4);                            // 2
    conv_h<<<8192, 256>>>(in_proj_w, w_all, (size_t)NL * 3 * EE / 4);    // 3
    conv_h<<<3072, 256>>>(out_w, wo_all, (size_t)NL * EE / 4);           // 4

    // 5: fused q0 + all k_l + all vT_l  (6656 CTAs, one launch)
    {
        dim3 grid(8, 64, 1 + 2 * NL);
        qkv_fused<<<grid, NTHR, GSMEM>>>(x, T, w_all, q, k_all, vT_all);
    }

    for (int l = 0; l < NL; l++) {
        // scores[b] = q_b @ k_b^T   (fp32)   <- launch 6 (l=0): profiled
        launch_gemm(q, (size_t)SQ * EDIM, k_all + (size_t)l * SZ, (size_t)SKV * EDIM,
                    sc, nullptr, (size_t)SQ * SKV,
                    SQ, SKV, EDIM, SKV, 1.f, nullptr, NB);
        softmax_h<<<NB * SQ, 256>>>(sc, p);
        // o[b] = attn_b @ vT_b^T
        launch_gemm(p, (size_t)SQ * SKV, vT_all + (size_t)l * SZ, (size_t)EDIM * SKV,
                    nullptr, o, (size_t)SQ * EDIM,
                    SQ, EDIM, SKV, EDIM, 1.f, nullptr, NB);
        // x = o @ out_w^T + out_b
        launch_gemm(o, 0, wo_all + (size_t)l * EE, 0,
                    nullptr, x, 0,
                    MTOT, EDIM, EDIM, EDIM, 1.f, out_b + (size_t)l * EDIM, 1);
        // q_{l+1} = (x @ Wq_{l+1}^T) * SCALE
        if (l + 1 < NL)
            launch_gemm(x, 0, w_all + (size_t)(l + 1) * 3 * EE, 0,
                        nullptr, q, 0,
                        MTOT, EDIM, EDIM, EDIM, SCALE_Q, nullptr, 1);
    }

    // logits = x @ lin_w^T + lin_b  (fp32 out)
    conv_h<<<8192, 256>>>(lin_w, lin, (size_t)VOC * EDIM / 4);
    launch_gemm(x, 0, lin, 0,
                logits, nullptr, 0,
                MTOT, VOC, EDIM, VOC, 1.f, lin_b, 1);
}